// round 3
// baseline (speedup 1.0000x reference)
#include <cuda_runtime.h>
#include <cuda_bf16.h>

// NBVLoss: weighted BCE reduction (HBM-bound streaming sum).
//   out = 10 * sum_{t==1} -max(log(p), -100) + 1 * sum_{t==0} -max(log(1-p), -100)
// target is exactly 0/1 -> one MUFU.LG2 per element; math is fully hidden.
// R3: 4x manual unroll (8 batched LDG.128 -> MLP_p1~8) + __ldcs streaming
// hints to squeeze the last ~9% of HBM bandwidth.

static __device__ __forceinline__ float bce_contrib(float p, float t) {
    bool is_one = (t != 0.0f);
    float x = is_one ? p : (1.0f - p);
    float l = __logf(x);              // MUFU.LG2 + FMUL(ln2)
    l = fmaxf(l, -100.0f);            // never binds (p in [1e-6, 1-1e-6])
    float w = is_one ? 10.0f : 1.0f;
    return -w * l;
}

static __device__ __forceinline__ float bce4(float4 pv, float4 tv) {
    return bce_contrib(pv.x, tv.x) + bce_contrib(pv.y, tv.y)
         + bce_contrib(pv.z, tv.z) + bce_contrib(pv.w, tv.w);
}

__global__ void __launch_bounds__(256)
nbv_loss_kernel(const float4* __restrict__ pred,
                const float4* __restrict__ targ,
                float* __restrict__ out,
                int n4) {
    float acc = 0.0f;
    const int stride = gridDim.x * blockDim.x;
    int i = blockIdx.x * blockDim.x + threadIdx.x;

    // Main loop: 4 iterations unrolled -> 8 independent LDG.128 in flight.
    for (; i + 3 * stride < n4; i += 4 * stride) {
        float4 p0 = __ldcs(&pred[i]);
        float4 p1 = __ldcs(&pred[i + stride]);
        float4 p2 = __ldcs(&pred[i + 2 * stride]);
        float4 p3 = __ldcs(&pred[i + 3 * stride]);
        float4 t0 = __ldcs(&targ[i]);
        float4 t1 = __ldcs(&targ[i + stride]);
        float4 t2 = __ldcs(&targ[i + 2 * stride]);
        float4 t3 = __ldcs(&targ[i + 3 * stride]);
        acc += bce4(p0, t0);
        acc += bce4(p1, t1);
        acc += bce4(p2, t2);
        acc += bce4(p3, t3);
    }
    // Remainder
    for (; i < n4; i += stride) {
        float4 pv = __ldcs(&pred[i]);
        float4 tv = __ldcs(&targ[i]);
        acc += bce4(pv, tv);
    }

    // warp reduction
    #pragma unroll
    for (int off = 16; off > 0; off >>= 1)
        acc += __shfl_xor_sync(0xFFFFFFFFu, acc, off);

    __shared__ float warp_sums[8];
    int lane = threadIdx.x & 31;
    int wid  = threadIdx.x >> 5;
    if (lane == 0) warp_sums[wid] = acc;
    __syncthreads();

    if (wid == 0) {
        float v = (lane < 8) ? warp_sums[lane] : 0.0f;
        #pragma unroll
        for (int off = 4; off > 0; off >>= 1)
            v += __shfl_xor_sync(0xFFFFFFFFu, v, off);
        if (lane == 0)
            atomicAdd(out, v);
    }
}

extern "C" void kernel_launch(void* const* d_in, const int* in_sizes, int n_in,
                              void* d_out, int out_size) {
    const float4* pred = (const float4*)d_in[0];
    const float4* targ = (const float4*)d_in[1];
    float* out = (float*)d_out;

    int n = in_sizes[0];           // 134217728, divisible by 4
    int n4 = n >> 2;               // 33554432 float4 elements

    cudaMemsetAsync(out, 0, sizeof(float));

    const int threads = 256;
    const int blocks = 148 * 32;   // 4736 blocks, grid-stride
    nbv_loss_kernel<<<blocks, threads>>>(pred, targ, out, n4);
}